// round 9
// baseline (speedup 1.0000x reference)
#include <cuda_runtime.h>

// Ragged segment mean — persistent CTAs with dynamic work-stealing.
//   seq:   [B=2048, L=512, D=512] fp32   (d_in[0])
//   begin: [B] int32                      (d_in[1])
//   end:   [B] int32                      (d_in[2])
//   out:   [B, D] fp32 = mean(seq[b, begin[b]:end[b], :], axis=0)
//
// Work items = even-split chunks (R7 scheme, best measured): item id ->
// (b = id/8, c = id%8), rows [begin + len*c/8, begin + len*(c+1)/8).
// 2432 persistent CTAs claim items from a global atomic counter; the
// next claim is issued BEFORE processing the current item (double-
// buffered smem slot) so ATOMG latency + begin/end loads overlap the
// ~1.5us of streaming. Partials pre-scaled by 1/len, merged with one
// red.global.add.v4.f32 per thread into a memset-zeroed out.

#define B_DIM   2048
#define L_DIM   512
#define D_DIM   512
#define THREADS 128                 // D_DIM / 4 lanes of float4
#define NSPLIT  8
#define NITEMS  (B_DIM * NSPLIT)    // 16384
#define GRID    (152 * 16)          // full-occupancy persistent wave

__device__ unsigned g_work_ctr;

__global__ __launch_bounds__(THREADS)
void ragged_mean_persistent(const float* __restrict__ seq,
                            const int* __restrict__ begin,
                            const int* __restrict__ end,
                            float* __restrict__ out) {
    __shared__ int s_item[2];
    const int t = threadIdx.x;      // owns columns [4t, 4t+4)

    if (t == 0) s_item[0] = (int)atomicAdd(&g_work_ctr, 1u);
    __syncthreads();

    int buf = 0;
    for (;;) {
        const int id = s_item[buf];
        if (id >= NITEMS) break;

        // Claim the NEXT item now; its ATOMG latency overlaps this item's work.
        if (t == 0) s_item[buf ^ 1] = (int)atomicAdd(&g_work_ctr, 1u);

        const int b   = id >> 3;            // id / NSPLIT
        const int c   = id & (NSPLIT - 1);  // id % NSPLIT
        const int sb  = begin[b];
        const int eb  = end[b];
        const int len = eb - sb;            // in [1, 256]

        const int s = sb + (len * c) / NSPLIT;
        const int e = sb + (len * (c + 1)) / NSPLIT;

        if (s < e) {
            const float4* base =
                reinterpret_cast<const float4*>(seq + (size_t)b * L_DIM * D_DIM) + t;

            float ax = 0.f, ay = 0.f, az = 0.f, aw = 0.f;

            int l = s;
            for (; l + 4 <= e; l += 4) {
                float4 v0 = __ldcs(&base[(size_t)(l + 0) * (D_DIM / 4)]);
                float4 v1 = __ldcs(&base[(size_t)(l + 1) * (D_DIM / 4)]);
                float4 v2 = __ldcs(&base[(size_t)(l + 2) * (D_DIM / 4)]);
                float4 v3 = __ldcs(&base[(size_t)(l + 3) * (D_DIM / 4)]);
                ax += v0.x + v1.x + v2.x + v3.x;
                ay += v0.y + v1.y + v2.y + v3.y;
                az += v0.z + v1.z + v2.z + v3.z;
                aw += v0.w + v1.w + v2.w + v3.w;
            }
            for (; l < e; ++l) {
                float4 v = __ldcs(&base[(size_t)l * (D_DIM / 4)]);
                ax += v.x; ay += v.y; az += v.z; aw += v.w;
            }

            const float inv = 1.0f / (float)len;
            ax *= inv; ay *= inv; az *= inv; aw *= inv;

            float* dst = out + (size_t)b * D_DIM + 4 * t;  // 16B aligned
            asm volatile("red.global.add.v4.f32 [%0], {%1, %2, %3, %4};"
                         :: "l"(dst), "f"(ax), "f"(ay), "f"(az), "f"(aw)
                         : "memory");
        }

        __syncthreads();   // orders lane 0's next-item write vs everyone's read
        buf ^= 1;
    }
}

extern "C" void kernel_launch(void* const* d_in, const int* in_sizes, int n_in,
                              void* d_out, int out_size) {
    const float* seq   = (const float*)d_in[0];
    const int*   begin = (const int*)d_in[1];
    const int*   end   = (const int*)d_in[2];
    float*       out   = (float*)d_out;

    static unsigned* ctr_addr = nullptr;
    if (!ctr_addr) cudaGetSymbolAddress((void**)&ctr_addr, g_work_ctr);

    // Reset work counter and zero the accumulation target (both capturable).
    cudaMemsetAsync(ctr_addr, 0, sizeof(unsigned));
    cudaMemsetAsync(d_out, 0, (size_t)B_DIM * D_DIM * sizeof(float));

    ragged_mean_persistent<<<GRID, THREADS>>>(seq, begin, end, out);
}

// round 10
// speedup vs baseline: 1.0718x; 1.0718x over previous
#include <cuda_runtime.h>

// Ragged segment mean — R6 scheme (even-split NSPLIT=8 + memset + REDG.v4)
// with deeper per-warp MLP (unroll x8) and a linear, locality-friendly grid.
//   seq:   [B=2048, L=512, D=512] fp32   (d_in[0])
//   begin: [B] int32                      (d_in[1])
//   end:   [B] int32                      (d_in[2])
//   out:   [B, D] fp32 = mean(seq[b, begin[b]:end[b], :], axis=0)
//
// Grid = B*8 linear CTAs; CTA id -> (b = id>>3, c = id&7); chunk c covers
// [begin + len*c/8, begin + len*(c+1)/8)  (<=32 rows, no empties).
// Main loop issues 8 independent LDG.128 per thread per iteration to
// deepen the in-flight load window (front-batched MLP_p1=8).

#define B_DIM   2048
#define L_DIM   512
#define D_DIM   512
#define THREADS 128          // D_DIM / 4 lanes of float4
#define NSPLIT  8
#define ROWS4   (D_DIM / 4)  // row stride in float4 units = 128

__global__ __launch_bounds__(THREADS)
void ragged_mean_chunk_kernel(const float* __restrict__ seq,
                              const int* __restrict__ begin,
                              const int* __restrict__ end,
                              float* __restrict__ out) {
    const int id = blockIdx.x;
    const int b  = id >> 3;            // id / NSPLIT
    const int c  = id & (NSPLIT - 1);  // id % NSPLIT
    const int t  = threadIdx.x;        // owns columns [4t, 4t+4)

    const int sb  = begin[b];
    const int eb  = end[b];
    const int len = eb - sb;           // in [1, 256]

    const int s = sb + (len * c) / NSPLIT;
    const int e = sb + (len * (c + 1)) / NSPLIT;
    if (s >= e) return;                // only when len < NSPLIT

    const float4* base =
        reinterpret_cast<const float4*>(seq + (size_t)b * L_DIM * D_DIM) + t;

    // Two accumulator trees to keep FADD chains short.
    float ax0 = 0.f, ay0 = 0.f, az0 = 0.f, aw0 = 0.f;
    float ax1 = 0.f, ay1 = 0.f, az1 = 0.f, aw1 = 0.f;

    int l = s;
    // Main loop: 8 independent LDG.128 per thread per iteration.
    for (; l + 8 <= e; l += 8) {
        float4 v0 = __ldcs(&base[(size_t)(l + 0) * ROWS4]);
        float4 v1 = __ldcs(&base[(size_t)(l + 1) * ROWS4]);
        float4 v2 = __ldcs(&base[(size_t)(l + 2) * ROWS4]);
        float4 v3 = __ldcs(&base[(size_t)(l + 3) * ROWS4]);
        float4 v4 = __ldcs(&base[(size_t)(l + 4) * ROWS4]);
        float4 v5 = __ldcs(&base[(size_t)(l + 5) * ROWS4]);
        float4 v6 = __ldcs(&base[(size_t)(l + 6) * ROWS4]);
        float4 v7 = __ldcs(&base[(size_t)(l + 7) * ROWS4]);
        ax0 += v0.x + v1.x + v2.x + v3.x;
        ay0 += v0.y + v1.y + v2.y + v3.y;
        az0 += v0.z + v1.z + v2.z + v3.z;
        aw0 += v0.w + v1.w + v2.w + v3.w;
        ax1 += v4.x + v5.x + v6.x + v7.x;
        ay1 += v4.y + v5.y + v6.y + v7.y;
        az1 += v4.z + v5.z + v6.z + v7.z;
        aw1 += v4.w + v5.w + v6.w + v7.w;
    }
    if (l + 4 <= e) {
        float4 v0 = __ldcs(&base[(size_t)(l + 0) * ROWS4]);
        float4 v1 = __ldcs(&base[(size_t)(l + 1) * ROWS4]);
        float4 v2 = __ldcs(&base[(size_t)(l + 2) * ROWS4]);
        float4 v3 = __ldcs(&base[(size_t)(l + 3) * ROWS4]);
        ax0 += v0.x + v1.x + v2.x + v3.x;
        ay0 += v0.y + v1.y + v2.y + v3.y;
        az0 += v0.z + v1.z + v2.z + v3.z;
        aw0 += v0.w + v1.w + v2.w + v3.w;
        l += 4;
    }
    for (; l < e; ++l) {
        float4 v = __ldcs(&base[(size_t)l * ROWS4]);
        ax1 += v.x; ay1 += v.y; az1 += v.z; aw1 += v.w;
    }

    const float inv = 1.0f / (float)len;
    const float ax = (ax0 + ax1) * inv;
    const float ay = (ay0 + ay1) * inv;
    const float az = (az0 + az1) * inv;
    const float aw = (aw0 + aw1) * inv;

    float* dst = out + (size_t)b * D_DIM + 4 * t;  // 16B aligned
    asm volatile("red.global.add.v4.f32 [%0], {%1, %2, %3, %4};"
                 :: "l"(dst), "f"(ax), "f"(ay), "f"(az), "f"(aw)
                 : "memory");
}

extern "C" void kernel_launch(void* const* d_in, const int* in_sizes, int n_in,
                              void* d_out, int out_size) {
    const float* seq   = (const float*)d_in[0];
    const int*   begin = (const int*)d_in[1];
    const int*   end   = (const int*)d_in[2];
    float*       out   = (float*)d_out;

    // Zero the accumulation target (async, graph-capturable)
    cudaMemsetAsync(d_out, 0, (size_t)B_DIM * D_DIM * sizeof(float));

    ragged_mean_chunk_kernel<<<B_DIM * NSPLIT, THREADS>>>(seq, begin, end, out);
}